// round 1
// baseline (speedup 1.0000x reference)
#include <cuda_runtime.h>
#include <cstdint>

#define NEG_INF (-1e30f)

constexpr int B = 32;
constexpr int L = 4096;
constexpr int D = 1024;

constexpr int NCHUNK = 16;                 // chunks per batch row
constexpr int ROWS_PER_BLOCK = L / NCHUNK; // 256
constexpr int THREADS = 256;
constexpr int WARPS = THREADS / 32;        // 8
constexpr int ROWS_PER_WARP = ROWS_PER_BLOCK / WARPS; // 32
constexpr int NPART = B * NCHUNK;          // 512 partial blocks

// Scratch (no allocations allowed in kernel_launch)
__device__ float g_scores[B * L];
__device__ float g_pacc[NPART][D];
__device__ float g_pm[NPART];
__device__ float g_pz[NPART];

__global__ __launch_bounds__(THREADS, 2)
void attn_pool_pass1(const float* __restrict__ seq,
                     const float* __restrict__ vec,
                     const int*   __restrict__ mask) {
    const int b     = blockIdx.x / NCHUNK;
    const int chunk = blockIdx.x % NCHUNK;
    const int tid   = threadIdx.x;
    const int wid   = tid >> 5;
    const int lane  = tid & 31;

    __shared__ float accS[D];
    __shared__ float m_sh[WARPS];
    __shared__ float z_sh[WARPS];
    for (int i = tid; i < D; i += THREADS) accS[i] = 0.0f;

    // vector[b] held in registers: lane owns float4 indices {k*32+lane}, k=0..7
    const float4* vec4 = reinterpret_cast<const float4*>(vec + (size_t)b * D);
    float4 v[8];
#pragma unroll
    for (int k = 0; k < 8; k++) v[k] = vec4[k * 32 + lane];

    // Prefetch this warp's 32 mask values: lane i holds mask for row i
    const int row0 = chunk * ROWS_PER_BLOCK + wid * ROWS_PER_WARP;
    const int my_mask = mask[(size_t)b * L + row0 + lane];

    float m = NEG_INF;
    float z = 0.0f;
    float4 acc[8];
#pragma unroll
    for (int k = 0; k < 8; k++) acc[k] = make_float4(0.f, 0.f, 0.f, 0.f);

    for (int i = 0; i < ROWS_PER_WARP; i++) {
        const int l = row0 + i;
        const int mk = __shfl_sync(0xffffffffu, my_mask, i);
        if (mk == 0) {
            // masked row: exactly zero weight; no sequence read needed
            if (lane == 0) g_scores[(size_t)b * L + l] = NEG_INF;
            continue;
        }
        const float4* s4 =
            reinterpret_cast<const float4*>(seq + ((size_t)b * L + l) * D);
        float4 x[8];
#pragma unroll
        for (int k = 0; k < 8; k++) x[k] = s4[k * 32 + lane];

        float dot = 0.0f;
#pragma unroll
        for (int k = 0; k < 8; k++) {
            dot += x[k].x * v[k].x + x[k].y * v[k].y
                 + x[k].z * v[k].z + x[k].w * v[k].w;
        }
#pragma unroll
        for (int o = 16; o > 0; o >>= 1)
            dot += __shfl_xor_sync(0xffffffffu, dot, o);

        if (lane == 0) g_scores[(size_t)b * L + l] = dot;

        // online softmax update (dot uniform across the warp -> no divergence)
        if (dot > m) {
            const float scale = __expf(m - dot);   // new element has weight 1
            z = z * scale + 1.0f;
#pragma unroll
            for (int k = 0; k < 8; k++) {
                acc[k].x = acc[k].x * scale + x[k].x;
                acc[k].y = acc[k].y * scale + x[k].y;
                acc[k].z = acc[k].z * scale + x[k].z;
                acc[k].w = acc[k].w * scale + x[k].w;
            }
            m = dot;
        } else {
            const float e = __expf(dot - m);
            z += e;
#pragma unroll
            for (int k = 0; k < 8; k++) {
                acc[k].x += e * x[k].x;
                acc[k].y += e * x[k].y;
                acc[k].z += e * x[k].z;
                acc[k].w += e * x[k].w;
            }
        }
    }

    // Merge 8 warps within the block
    if (lane == 0) { m_sh[wid] = m; z_sh[wid] = z; }
    __syncthreads();

    float m_blk = NEG_INF;
#pragma unroll
    for (int j = 0; j < WARPS; j++) m_blk = fmaxf(m_blk, m_sh[j]);
    float z_blk = 0.0f;
#pragma unroll
    for (int j = 0; j < WARPS; j++) z_blk += z_sh[j] * __expf(m_sh[j] - m_blk);

    const float sw = __expf(m - m_blk);   // rescale this warp's acc to m_blk
#pragma unroll
    for (int k = 0; k < 8; k++) {
        const int c = 4 * (k * 32 + lane);
        atomicAdd(&accS[c + 0], acc[k].x * sw);
        atomicAdd(&accS[c + 1], acc[k].y * sw);
        atomicAdd(&accS[c + 2], acc[k].z * sw);
        atomicAdd(&accS[c + 3], acc[k].w * sw);
    }
    __syncthreads();

    const int pb = blockIdx.x;
    const float4* aS = reinterpret_cast<const float4*>(accS);
    float4* pa = reinterpret_cast<float4*>(g_pacc[pb]);
    for (int i = tid; i < D / 4; i += THREADS) pa[i] = aS[i];
    if (tid == 0) { g_pm[pb] = m_blk; g_pz[pb] = z_blk; }
}

__global__ __launch_bounds__(THREADS)
void attn_pool_pass2(float* __restrict__ out_pooled,   // [B, D]
                     float* __restrict__ out_weights)  // [B, L]
{
    const int b = blockIdx.x;
    const int tid = threadIdx.x;

    __shared__ float sc_sh[NCHUNK];
    __shared__ float stats[2]; // m_final, invZ

    if (tid == 0) {
        float m_f = NEG_INF;
#pragma unroll
        for (int j = 0; j < NCHUNK; j++) m_f = fmaxf(m_f, g_pm[b * NCHUNK + j]);
        float Z = 0.0f;
#pragma unroll
        for (int j = 0; j < NCHUNK; j++) {
            const float s = __expf(g_pm[b * NCHUNK + j] - m_f);
            sc_sh[j] = s;
            Z += g_pz[b * NCHUNK + j] * s;
        }
        stats[0] = m_f;
        stats[1] = 1.0f / Z;
    }
    __syncthreads();
    const float m_f  = stats[0];
    const float invZ = stats[1];

    // pooled: reduce NCHUNK partial accumulators
    for (int d = tid; d < D; d += THREADS) {
        float s = 0.0f;
#pragma unroll
        for (int j = 0; j < NCHUNK; j++)
            s += g_pacc[b * NCHUNK + j][d] * sc_sh[j];
        out_pooled[(size_t)b * D + d] = s * invZ;
    }

    // weights: normalize stored scores (masked rows -> exp(-1e30-m)=0 exactly)
    for (int l = tid; l < L; l += THREADS) {
        const float s = g_scores[(size_t)b * L + l];
        out_weights[(size_t)b * L + l] = __expf(s - m_f) * invZ;
    }
}

extern "C" void kernel_launch(void* const* d_in, const int* in_sizes, int n_in,
                              void* d_out, int out_size) {
    const float* seq  = (const float*)d_in[0];
    const float* vec  = (const float*)d_in[1];
    const int*   mask = (const int*)d_in[2];

    float* out_pooled  = (float*)d_out;            // [B, D]
    float* out_weights = out_pooled + (size_t)B * D; // [B, L]

    attn_pool_pass1<<<B * NCHUNK, THREADS>>>(seq, vec, mask);
    attn_pool_pass2<<<B, THREADS>>>(out_pooled, out_weights);
}

// round 2
// speedup vs baseline: 1.1926x; 1.1926x over previous
#include <cuda_runtime.h>
#include <cstdint>

#define NEG_INF (-1e30f)

constexpr int B = 32;
constexpr int L = 4096;
constexpr int D = 1024;

constexpr int THREADS1 = 128;
constexpr int WARPS1 = 4;
constexpr int ROWS_PER_BLOCK = 64;
constexpr int NCHUNK = L / ROWS_PER_BLOCK;   // 64
constexpr int NPART = B * NCHUNK;            // 2048

constexpr int P2_SPLIT = 16;
constexpr int THREADS2 = 256;

// Scratch (no allocations allowed in kernel_launch)
__device__ float g_scores[B * L];
__device__ float g_pacc[NPART][D];
__device__ float g_pm[NPART];
__device__ float g_pz[NPART];

__global__ __launch_bounds__(THREADS1, 4)
void attn_pool_pass1(const float* __restrict__ seq,
                     const float* __restrict__ vec,
                     const int*   __restrict__ mask) {
    const int blk   = blockIdx.x;
    const int b     = blk / NCHUNK;
    const int chunk = blk % NCHUNK;
    const int tid   = threadIdx.x;
    const int wid   = tid >> 5;
    const int lane  = tid & 31;
    const int row0  = chunk * ROWS_PER_BLOCK;

    __shared__ float accS[D];
    __shared__ int   row_list[ROWS_PER_BLOCK];
    __shared__ int   cnt_sh[2];
    __shared__ float m_sh[WARPS1], z_sh[WARPS1];

    for (int i = tid; i < D; i += THREADS1) accS[i] = 0.0f;

    // ---- compaction of unmasked rows (64 rows handled by warps 0,1) ----
    int mk = 0;
    if (tid < ROWS_PER_BLOCK)
        mk = mask[(size_t)b * L + row0 + tid];
    const unsigned bal = __ballot_sync(0xffffffffu, mk != 0);
    if (wid < 2 && lane == 0) cnt_sh[wid] = __popc(bal);
    if (tid < ROWS_PER_BLOCK && mk == 0)
        g_scores[(size_t)b * L + row0 + tid] = NEG_INF;
    __syncthreads();
    const int n_rows = cnt_sh[0] + cnt_sh[1];
    if (tid < ROWS_PER_BLOCK && mk != 0) {
        const int base = (wid == 1) ? cnt_sh[0] : 0;
        const int pos  = base + __popc(bal & ((1u << lane) - 1u));
        row_list[pos] = tid;
    }
    __syncthreads();

    // vector[b] in registers: lane owns float4 indices {k*32+lane}, k=0..7
    const float4* vec4 = reinterpret_cast<const float4*>(vec + (size_t)b * D);
    float4 v[8];
#pragma unroll
    for (int k = 0; k < 8; k++) v[k] = vec4[k * 32 + lane];

    float m = NEG_INF;
    float z = 0.0f;
    float4 acc[8];
#pragma unroll
    for (int k = 0; k < 8; k++) acc[k] = make_float4(0.f, 0.f, 0.f, 0.f);

    // warps pull unmasked rows strided -> even work split (+-1 row)
    for (int j = wid; j < n_rows; j += WARPS1) {
        const int l = row0 + row_list[j];
        const float4* s4 =
            reinterpret_cast<const float4*>(seq + ((size_t)b * L + l) * D);
        float4 x[8];
#pragma unroll
        for (int k = 0; k < 8; k++) x[k] = s4[k * 32 + lane];

        float dot = 0.0f;
#pragma unroll
        for (int k = 0; k < 8; k++) {
            dot += x[k].x * v[k].x + x[k].y * v[k].y
                 + x[k].z * v[k].z + x[k].w * v[k].w;
        }
#pragma unroll
        for (int o = 16; o > 0; o >>= 1)
            dot += __shfl_xor_sync(0xffffffffu, dot, o);

        if (lane == 0) g_scores[(size_t)b * L + l] = dot;

        if (dot > m) {
            const float scale = __expf(m - dot);
            z = z * scale + 1.0f;
#pragma unroll
            for (int k = 0; k < 8; k++) {
                acc[k].x = acc[k].x * scale + x[k].x;
                acc[k].y = acc[k].y * scale + x[k].y;
                acc[k].z = acc[k].z * scale + x[k].z;
                acc[k].w = acc[k].w * scale + x[k].w;
            }
            m = dot;
        } else {
            const float e = __expf(dot - m);
            z += e;
#pragma unroll
            for (int k = 0; k < 8; k++) {
                acc[k].x += e * x[k].x;
                acc[k].y += e * x[k].y;
                acc[k].z += e * x[k].z;
                acc[k].w += e * x[k].w;
            }
        }
    }

    // ---- merge 4 warps ----
    if (lane == 0) { m_sh[wid] = m; z_sh[wid] = z; }
    __syncthreads();

    float m_blk = NEG_INF;
#pragma unroll
    for (int j = 0; j < WARPS1; j++) m_blk = fmaxf(m_blk, m_sh[j]);
    float z_blk = 0.0f;
#pragma unroll
    for (int j = 0; j < WARPS1; j++) z_blk += z_sh[j] * __expf(m_sh[j] - m_blk);

    const float sw = __expf(m - m_blk);
#pragma unroll
    for (int k = 0; k < 8; k++) {
        const int c = 4 * (k * 32 + lane);
        atomicAdd(&accS[c + 0], acc[k].x * sw);
        atomicAdd(&accS[c + 1], acc[k].y * sw);
        atomicAdd(&accS[c + 2], acc[k].z * sw);
        atomicAdd(&accS[c + 3], acc[k].w * sw);
    }
    __syncthreads();

    const float4* aS = reinterpret_cast<const float4*>(accS);
    float4* pa = reinterpret_cast<float4*>(g_pacc[blk]);
    for (int i = tid; i < D / 4; i += THREADS1) pa[i] = aS[i];
    if (tid == 0) { g_pm[blk] = m_blk; g_pz[blk] = z_blk; }
}

__global__ __launch_bounds__(THREADS2)
void attn_pool_pass2(float* __restrict__ out_pooled,   // [B, D]
                     float* __restrict__ out_weights)  // [B, L]
{
    const int b    = blockIdx.x / P2_SPLIT;
    const int part = blockIdx.x % P2_SPLIT;
    const int tid  = threadIdx.x;

    __shared__ float sh_pm[NCHUNK], sh_pz[NCHUNK], sh_sc[NCHUNK];
    __shared__ float sh_stats[2];
    __shared__ float sh_pool[4][D / P2_SPLIT];

    if (tid < NCHUNK) {
        sh_pm[tid] = g_pm[b * NCHUNK + tid];
        sh_pz[tid] = g_pz[b * NCHUNK + tid];
    }
    __syncthreads();

    if (tid < 32) {
        const float a = sh_pm[tid];
        const float c = sh_pm[tid + 32];
        float mloc = fmaxf(a, c);
#pragma unroll
        for (int o = 16; o > 0; o >>= 1)
            mloc = fmaxf(mloc, __shfl_xor_sync(0xffffffffu, mloc, o));
        const float s0 = __expf(a - mloc);
        const float s1 = __expf(c - mloc);
        sh_sc[tid]      = s0;
        sh_sc[tid + 32] = s1;
        float zl = sh_pz[tid] * s0 + sh_pz[tid + 32] * s1;
#pragma unroll
        for (int o = 16; o > 0; o >>= 1)
            zl += __shfl_xor_sync(0xffffffffu, zl, o);
        if (tid == 0) { sh_stats[0] = mloc; sh_stats[1] = 1.0f / zl; }
    }
    __syncthreads();
    const float m_f  = sh_stats[0];
    const float invZ = sh_stats[1];

    // pooled: 64 cols per block, 4 thread-groups split the 64 partials
    {
        const int c = tid & 63;
        const int g = tid >> 6;          // 0..3
        float s = 0.0f;
#pragma unroll
        for (int jj = 0; jj < NCHUNK / 4; jj++) {
            const int j = g * (NCHUNK / 4) + jj;
            s += g_pacc[b * NCHUNK + j][part * 64 + c] * sh_sc[j];
        }
        sh_pool[g][c] = s;
    }
    __syncthreads();
    if (tid < 64) {
        const float s = sh_pool[0][tid] + sh_pool[1][tid]
                      + sh_pool[2][tid] + sh_pool[3][tid];
        out_pooled[(size_t)b * D + part * 64 + tid] = s * invZ;
    }

    // weights: 256 per block (L / 16)
    {
        const int l = part * (L / P2_SPLIT) + tid;
        const float sc = g_scores[(size_t)b * L + l];
        out_weights[(size_t)b * L + l] = __expf(sc - m_f) * invZ;
    }
}

extern "C" void kernel_launch(void* const* d_in, const int* in_sizes, int n_in,
                              void* d_out, int out_size) {
    const float* seq  = (const float*)d_in[0];
    const float* vec  = (const float*)d_in[1];
    const int*   mask = (const int*)d_in[2];

    float* out_pooled  = (float*)d_out;               // [B, D]
    float* out_weights = out_pooled + (size_t)B * D;  // [B, L]

    attn_pool_pass1<<<B * NCHUNK, THREADS1>>>(seq, vec, mask);
    attn_pool_pass2<<<B * P2_SPLIT, THREADS2>>>(out_pooled, out_weights);
}

// round 3
// speedup vs baseline: 1.3772x; 1.1548x over previous
#include <cuda_runtime.h>
#include <cstdint>

#define NEG_INF (-1e30f)

constexpr int B = 32;
constexpr int L = 4096;
constexpr int D = 1024;

constexpr int THREADS1 = 128;
constexpr int WARPS1 = 4;
constexpr int ROWS_PER_BLOCK = 64;
constexpr int NCHUNK = L / ROWS_PER_BLOCK;   // 64
constexpr int NPART = B * NCHUNK;            // 2048

constexpr int P2_SPLIT = 32;
constexpr int THREADS2 = 256;

// Scratch (no allocations allowed in kernel_launch)
__device__ __align__(16) float g_scores[B * L];
__device__ __align__(16) float g_pacc[NPART][D];
__device__ float g_pm[NPART];
__device__ float g_pz[NPART];

__global__ __launch_bounds__(THREADS1, 4)
void attn_pool_pass1(const float* __restrict__ seq,
                     const float* __restrict__ vec,
                     const int*   __restrict__ mask) {
    const int blk   = blockIdx.x;
    const int b     = blk / NCHUNK;
    const int chunk = blk % NCHUNK;
    const int tid   = threadIdx.x;
    const int wid   = tid >> 5;
    const int lane  = tid & 31;
    const int row0  = chunk * ROWS_PER_BLOCK;

    __shared__ int   row_list[ROWS_PER_BLOCK];
    __shared__ int   cnt_sh[2];
    __shared__ float sp[2][WARPS1][8];   // parity-buffered partial dots

    // ---- compaction of unmasked rows ----
    int mk = 0;
    if (tid < ROWS_PER_BLOCK)
        mk = mask[(size_t)b * L + row0 + tid];
    const unsigned bal = __ballot_sync(0xffffffffu, mk != 0);
    if (wid < 2 && lane == 0) cnt_sh[wid] = __popc(bal);
    if (tid < ROWS_PER_BLOCK && mk == 0)
        g_scores[(size_t)b * L + row0 + tid] = NEG_INF;
    __syncthreads();
    const int n_rows = cnt_sh[0] + cnt_sh[1];
    if (tid < ROWS_PER_BLOCK && mk != 0) {
        const int base = (wid == 1) ? cnt_sh[0] : 0;
        row_list[base + __popc(bal & ((1u << lane) - 1u))] = tid;
    }
    __syncthreads();

    // D-split: warp w owns columns [w*256, (w+1)*256). Lane owns 2 float4s.
    const int fbase = wid * 64 + lane;  // float4 index within a row
    const float4* vec4 = reinterpret_cast<const float4*>(vec + (size_t)b * D);
    const float4 v0 = vec4[fbase];
    const float4 v1 = vec4[fbase + 32];

    float m = NEG_INF;
    float z = 0.0f;
    float4 a0 = make_float4(0.f, 0.f, 0.f, 0.f);
    float4 a1 = make_float4(0.f, 0.f, 0.f, 0.f);

    const float4* sbase =
        reinterpret_cast<const float4*>(seq + ((size_t)b * L + row0) * D);
    const int nR = (n_rows + 7) >> 3;

    for (int rd = 0; rd < nR; rd++) {
        const int p    = rd & 1;
        const int idx0 = rd * 8;

        // front-batched loads: 16 LDG.128 per warp (8 rows x 2)
        float4 x0[8], x1[8];
#pragma unroll
        for (int r = 0; r < 8; r++) {
            const int ii = idx0 + r;
            const int rl = row_list[(ii < n_rows) ? ii : 0];
            const float4* s4 = sbase + (size_t)rl * (D / 4);
            x0[r] = s4[fbase];
            x1[r] = s4[fbase + 32];
        }

        // partial dots over this warp's 256-col slice
#pragma unroll
        for (int r = 0; r < 8; r++) {
            float d = x0[r].x * v0.x + x0[r].y * v0.y
                    + x0[r].z * v0.z + x0[r].w * v0.w
                    + x1[r].x * v1.x + x1[r].y * v1.y
                    + x1[r].z * v1.z + x1[r].w * v1.w;
#pragma unroll
            for (int o = 16; o > 0; o >>= 1)
                d += __shfl_xor_sync(0xffffffffu, d, o);
            if (lane == 0) sp[p][wid][r] = d;
        }
        __syncthreads();

        // full dots (identical across all warps -> identical m,z everywhere)
        float dots[8];
#pragma unroll
        for (int r = 0; r < 8; r++) {
            dots[r] = (idx0 + r < n_rows)
                ? sp[p][0][r] + sp[p][1][r] + sp[p][2][r] + sp[p][3][r]
                : NEG_INF;
        }

        if (tid < 8 && idx0 + tid < n_rows) {
            const int l = row0 + row_list[idx0 + tid];
            g_scores[(size_t)b * L + l] =
                sp[p][0][tid] + sp[p][1][tid] + sp[p][2][tid] + sp[p][3][tid];
        }

        float rmax = dots[0];
#pragma unroll
        for (int r = 1; r < 8; r++) rmax = fmaxf(rmax, dots[r]);
        const float mnew  = fmaxf(m, rmax);
        const float scale = __expf(m - mnew);
        z *= scale;
        a0.x *= scale; a0.y *= scale; a0.z *= scale; a0.w *= scale;
        a1.x *= scale; a1.y *= scale; a1.z *= scale; a1.w *= scale;
#pragma unroll
        for (int r = 0; r < 8; r++) {
            const float e = __expf(dots[r] - mnew);
            z += e;
            a0.x += e * x0[r].x; a0.y += e * x0[r].y;
            a0.z += e * x0[r].z; a0.w += e * x0[r].w;
            a1.x += e * x1[r].x; a1.y += e * x1[r].y;
            a1.z += e * x1[r].z; a1.w += e * x1[r].w;
        }
        m = mnew;
    }

    // every warp writes its own slice; no cross-warp merge needed
    float4* pa = reinterpret_cast<float4*>(g_pacc[blk]);
    pa[fbase]      = a0;
    pa[fbase + 32] = a1;
    if (tid == 0) { g_pm[blk] = m; g_pz[blk] = z; }
}

__global__ __launch_bounds__(THREADS2)
void attn_pool_pass2(float* __restrict__ out_pooled,   // [B, D]
                     float* __restrict__ out_weights)  // [B, L]
{
    const int b    = blockIdx.x / P2_SPLIT;
    const int part = blockIdx.x % P2_SPLIT;
    const int tid  = threadIdx.x;

    __shared__ float sh_pm[NCHUNK], sh_pz[NCHUNK], sh_sc[NCHUNK];
    __shared__ float sh_stats[2];
    __shared__ float sh_pool[8][32];

    if (tid < NCHUNK) {
        sh_pm[tid] = g_pm[b * NCHUNK + tid];
        sh_pz[tid] = g_pz[b * NCHUNK + tid];
    }
    __syncthreads();

    if (tid < 32) {
        const float a = sh_pm[tid];
        const float c = sh_pm[tid + 32];
        float mloc = fmaxf(a, c);
#pragma unroll
        for (int o = 16; o > 0; o >>= 1)
            mloc = fmaxf(mloc, __shfl_xor_sync(0xffffffffu, mloc, o));
        const float s0 = __expf(a - mloc);
        const float s1 = __expf(c - mloc);
        sh_sc[tid]      = s0;
        sh_sc[tid + 32] = s1;
        float zl = sh_pz[tid] * s0 + sh_pz[tid + 32] * s1;
#pragma unroll
        for (int o = 16; o > 0; o >>= 1)
            zl += __shfl_xor_sync(0xffffffffu, zl, o);
        if (tid == 0) { sh_stats[0] = mloc; sh_stats[1] = 1.0f / zl; }
    }
    __syncthreads();
    const float m_f  = sh_stats[0];
    const float invZ = sh_stats[1];

    // pooled: 32 cols per block; 8 groups each sum 8 of the 64 partials
    {
        const int c = tid & 31;
        const int g = tid >> 5;
        float s = 0.0f;
#pragma unroll
        for (int jj = 0; jj < NCHUNK / 8; jj++) {
            const int j = g * (NCHUNK / 8) + jj;
            s += g_pacc[b * NCHUNK + j][part * 32 + c] * sh_sc[j];
        }
        sh_pool[g][c] = s;
    }
    __syncthreads();
    if (tid < 32) {
        float s = 0.0f;
#pragma unroll
        for (int g = 0; g < 8; g++) s += sh_pool[g][tid];
        out_pooled[(size_t)b * D + part * 32 + tid] = s * invZ;
    }

    // weights: 128 per block (L / 32)
    if (tid < L / P2_SPLIT) {
        const int l = part * (L / P2_SPLIT) + tid;
        const float sc = g_scores[(size_t)b * L + l];
        out_weights[(size_t)b * L + l] = __expf(sc - m_f) * invZ;
    }
}

extern "C" void kernel_launch(void* const* d_in, const int* in_sizes, int n_in,
                              void* d_out, int out_size) {
    const float* seq  = (const float*)d_in[0];
    const float* vec  = (const float*)d_in[1];
    const int*   mask = (const int*)d_in[2];

    float* out_pooled  = (float*)d_out;               // [B, D]
    float* out_weights = out_pooled + (size_t)B * D;  // [B, L]

    attn_pool_pass1<<<B * NCHUNK, THREADS1>>>(seq, vec, mask);
    attn_pool_pass2<<<B * P2_SPLIT, THREADS2>>>(out_pooled, out_weights);
}

// round 4
// speedup vs baseline: 1.4190x; 1.0304x over previous
#include <cuda_runtime.h>
#include <cstdint>

#define NEG_INF (-1e30f)

constexpr int B = 32;
constexpr int L = 4096;
constexpr int D = 1024;

constexpr int THREADS1 = 128;
constexpr int WARPS1 = 4;
constexpr int ROWS_PER_BLOCK = 64;
constexpr int NCHUNK = L / ROWS_PER_BLOCK;   // 64
constexpr int NPART = B * NCHUNK;            // 2048

constexpr int P2_SPLIT = 8;                  // 128 cols per block
constexpr int THREADS2 = 256;

// Scratch (no allocations allowed in kernel_launch)
__device__ __align__(16) float g_scores[B * L];
__device__ __align__(16) float g_pacc[NPART][D];
__device__ float g_pm[NPART];
__device__ float g_pz[NPART];

// ---- packed f32x2 helpers (PTX-only; ptxas never emits FFMA2 from C++) ----
__device__ __forceinline__ unsigned long long f2fma(unsigned long long a,
                                                    unsigned long long b,
                                                    unsigned long long c) {
    unsigned long long d;
    asm("fma.rn.f32x2 %0, %1, %2, %3;" : "=l"(d) : "l"(a), "l"(b), "l"(c));
    return d;
}
__device__ __forceinline__ unsigned long long f2mul(unsigned long long a,
                                                    unsigned long long b) {
    unsigned long long d;
    asm("mul.rn.f32x2 %0, %1, %2;" : "=l"(d) : "l"(a), "l"(b));
    return d;
}
__device__ __forceinline__ float f2sum(unsigned long long a) {
    unsigned lo, hi;
    asm("mov.b64 {%0, %1}, %2;" : "=r"(lo), "=r"(hi) : "l"(a));
    return __uint_as_float(lo) + __uint_as_float(hi);
}
__device__ __forceinline__ unsigned long long f2bcast(float f) {
    unsigned long long d;
    unsigned u = __float_as_uint(f);
    asm("mov.b64 %0, {%1, %1};" : "=l"(d) : "r"(u));
    return d;
}

__global__ __launch_bounds__(THREADS1, 4)
void attn_pool_pass1(const float* __restrict__ seq,
                     const float* __restrict__ vec,
                     const int*   __restrict__ mask) {
    const int blk   = blockIdx.x;
    const int b     = blk / NCHUNK;
    const int chunk = blk % NCHUNK;
    const int tid   = threadIdx.x;
    const int wid   = tid >> 5;
    const int lane  = tid & 31;
    const int row0  = chunk * ROWS_PER_BLOCK;

    __shared__ int row_list[ROWS_PER_BLOCK];
    __shared__ int cnt_sh[2];
    __shared__ __align__(16) float sp[2][8][4];   // [parity][row][warp]

    // ---- compaction of unmasked rows ----
    int mk = 0;
    if (tid < ROWS_PER_BLOCK)
        mk = mask[(size_t)b * L + row0 + tid];
    const unsigned bal = __ballot_sync(0xffffffffu, mk != 0);
    if (wid < 2 && lane == 0) cnt_sh[wid] = __popc(bal);
    if (tid < ROWS_PER_BLOCK && mk == 0)
        g_scores[(size_t)b * L + row0 + tid] = NEG_INF;
    __syncthreads();
    const int n_rows = cnt_sh[0] + cnt_sh[1];
    if (tid < ROWS_PER_BLOCK && mk != 0) {
        const int base = (wid == 1) ? cnt_sh[0] : 0;
        row_list[base + __popc(bal & ((1u << lane) - 1u))] = tid;
    }
    __syncthreads();

    // warp w owns cols [w*256,(w+1)*256); lane owns 2x16B (as u64 pairs)
    const int fbase = wid * 64 + lane;   // 16-byte-unit index within a row
    const ulonglong2* vec2 =
        reinterpret_cast<const ulonglong2*>(vec + (size_t)b * D);
    const ulonglong2 v0 = vec2[fbase];
    const ulonglong2 v1 = vec2[fbase + 32];

    float m = NEG_INF, z = 0.0f;
    ulonglong2 a0 = make_ulonglong2(0ull, 0ull);
    ulonglong2 a1 = make_ulonglong2(0ull, 0ull);

    const ulonglong2* sbase =
        reinterpret_cast<const ulonglong2*>(seq + ((size_t)b * L + row0) * D);
    const int nR = (n_rows + 7) >> 3;

    const unsigned b0 = lane & 1, b1 = (lane >> 1) & 1, b2 = (lane >> 2) & 1;

    for (int rd = 0; rd < nR; rd++) {
        const int p    = rd & 1;
        const int idx0 = rd * 8;

        // front-batched: 16 LDG.128 per warp
        ulonglong2 xa[8], xb[8];
#pragma unroll
        for (int r = 0; r < 8; r++) {
            const int ii = idx0 + r;
            const int rl = row_list[(ii < n_rows) ? ii : 0];
            const ulonglong2* s2 = sbase + (size_t)rl * (D / 4);
            xa[r] = s2[fbase];
            xb[r] = s2[fbase + 32];
        }

        // per-lane partial dots (f32x2)
        float pd[8];
#pragma unroll
        for (int r = 0; r < 8; r++) {
            unsigned long long d2 = f2mul(xa[r].x, v0.x);
            d2 = f2fma(xa[r].y, v0.y, d2);
            d2 = f2fma(xb[r].x, v1.x, d2);
            d2 = f2fma(xb[r].y, v1.y, d2);
            pd[r] = f2sum(d2);
        }

        // multi-value butterfly: fold rows with offsets 1,2,4; finish 8,16
        float q[4];
#pragma unroll
        for (int i = 0; i < 4; i++) {
            const float keep = b0 ? pd[2 * i + 1] : pd[2 * i];
            const float send = b0 ? pd[2 * i]     : pd[2 * i + 1];
            q[i] = keep + __shfl_xor_sync(0xffffffffu, send, 1);
        }
        float r01, r23;
        {
            float keep = b1 ? q[1] : q[0];
            float send = b1 ? q[0] : q[1];
            r01 = keep + __shfl_xor_sync(0xffffffffu, send, 2);
            keep = b1 ? q[3] : q[2];
            send = b1 ? q[2] : q[3];
            r23 = keep + __shfl_xor_sync(0xffffffffu, send, 2);
        }
        float t;
        {
            const float keep = b2 ? r23 : r01;
            const float send = b2 ? r01 : r23;
            t = keep + __shfl_xor_sync(0xffffffffu, send, 4);
        }
        t += __shfl_xor_sync(0xffffffffu, t, 8);
        t += __shfl_xor_sync(0xffffffffu, t, 16);
        // lane holds full slice-partial for row = lane&7
        if (lane < 8) sp[p][lane][wid] = t;
        __syncthreads();

        // full dot for row = lane&7 (one LDS.128)
        const int row = lane & 7;
        const float4 sq = *reinterpret_cast<const float4*>(&sp[p][row][0]);
        const float dot = sq.x + sq.y + sq.z + sq.w;

        if (wid == 0 && lane < 8 && idx0 + lane < n_rows)
            g_scores[(size_t)b * L + row0 + row_list[idx0 + lane]] = dot;

        const bool valid = (idx0 + row) < n_rows;
        const float dv = valid ? dot : NEG_INF;

        float rmax = dv;
        rmax = fmaxf(rmax, __shfl_xor_sync(0xffffffffu, rmax, 1));
        rmax = fmaxf(rmax, __shfl_xor_sync(0xffffffffu, rmax, 2));
        rmax = fmaxf(rmax, __shfl_xor_sync(0xffffffffu, rmax, 4));

        const float mnew  = fmaxf(m, rmax);
        const float scale = __expf(m - mnew);
        const float e     = __expf(dv - mnew);
        float es = e;
        es += __shfl_xor_sync(0xffffffffu, es, 1);
        es += __shfl_xor_sync(0xffffffffu, es, 2);
        es += __shfl_xor_sync(0xffffffffu, es, 4);
        z = z * scale + es;

        const unsigned long long s2v = f2bcast(scale);
        a0.x = f2mul(a0.x, s2v); a0.y = f2mul(a0.y, s2v);
        a1.x = f2mul(a1.x, s2v); a1.y = f2mul(a1.y, s2v);

#pragma unroll
        for (int r = 0; r < 8; r++) {
            const float er = __shfl_sync(0xffffffffu, e, r);
            const unsigned long long e2 = f2bcast(er);
            a0.x = f2fma(xa[r].x, e2, a0.x);
            a0.y = f2fma(xa[r].y, e2, a0.y);
            a1.x = f2fma(xb[r].x, e2, a1.x);
            a1.y = f2fma(xb[r].y, e2, a1.y);
        }
        m = mnew;
    }

    // each warp writes its own slice; m,z identical across warps
    ulonglong2* pa = reinterpret_cast<ulonglong2*>(g_pacc[blk]);
    pa[fbase]      = a0;
    pa[fbase + 32] = a1;
    if (tid == 0) { g_pm[blk] = m; g_pz[blk] = z; }
}

__global__ __launch_bounds__(THREADS2)
void attn_pool_pass2(float* __restrict__ out_pooled,   // [B, D]
                     float* __restrict__ out_weights)  // [B, L]
{
    const int b    = blockIdx.x / P2_SPLIT;
    const int part = blockIdx.x % P2_SPLIT;
    const int tid  = threadIdx.x;

    __shared__ float sh_pm[NCHUNK], sh_pz[NCHUNK], sh_sc[NCHUNK];
    __shared__ float sh_stats[2];
    __shared__ __align__(16) float4 sh_pool[8][32];

    if (tid < NCHUNK) {
        sh_pm[tid] = g_pm[b * NCHUNK + tid];
        sh_pz[tid] = g_pz[b * NCHUNK + tid];
    }
    __syncthreads();

    if (tid < 32) {
        const float a = sh_pm[tid];
        const float c = sh_pm[tid + 32];
        float mloc = fmaxf(a, c);
#pragma unroll
        for (int o = 16; o > 0; o >>= 1)
            mloc = fmaxf(mloc, __shfl_xor_sync(0xffffffffu, mloc, o));
        const float s0 = __expf(a - mloc);
        const float s1 = __expf(c - mloc);
        sh_sc[tid]      = s0;
        sh_sc[tid + 32] = s1;
        float zl = sh_pz[tid] * s0 + sh_pz[tid + 32] * s1;
#pragma unroll
        for (int o = 16; o > 0; o >>= 1)
            zl += __shfl_xor_sync(0xffffffffu, zl, o);
        if (tid == 0) { sh_stats[0] = mloc; sh_stats[1] = 1.0f / zl; }
    }
    __syncthreads();
    const float m_f  = sh_stats[0];
    const float invZ = sh_stats[1];

    // pooled: 128 cols per block as 32 float4; 8 groups x 8 partials
    {
        const int c4 = tid & 31;
        const int g  = tid >> 5;
        float4 s = make_float4(0.f, 0.f, 0.f, 0.f);
#pragma unroll
        for (int jj = 0; jj < NCHUNK / 8; jj++) {
            const int j = g * (NCHUNK / 8) + jj;
            const float4 t = *reinterpret_cast<const float4*>(
                &g_pacc[b * NCHUNK + j][part * 128 + 4 * c4]);
            const float w = sh_sc[j];
            s.x += w * t.x; s.y += w * t.y; s.z += w * t.z; s.w += w * t.w;
        }
        sh_pool[g][c4] = s;
    }
    __syncthreads();
    if (tid < 32) {
        float4 s = sh_pool[0][tid];
#pragma unroll
        for (int g = 1; g < 8; g++) {
            const float4 t = sh_pool[g][tid];
            s.x += t.x; s.y += t.y; s.z += t.z; s.w += t.w;
        }
        s.x *= invZ; s.y *= invZ; s.z *= invZ; s.w *= invZ;
        reinterpret_cast<float4*>(out_pooled)[b * (D / 4) + part * 32 + tid] = s;
    }

    // weights: 512 per block as float2 per thread
    {
        const int l0 = part * (L / P2_SPLIT) + tid * 2;
        const float2 sc2 =
            *reinterpret_cast<const float2*>(&g_scores[(size_t)b * L + l0]);
        float2 w2;
        w2.x = __expf(sc2.x - m_f) * invZ;
        w2.y = __expf(sc2.y - m_f) * invZ;
        *reinterpret_cast<float2*>(&out_weights[(size_t)b * L + l0]) = w2;
    }
}

extern "C" void kernel_launch(void* const* d_in, const int* in_sizes, int n_in,
                              void* d_out, int out_size) {
    const float* seq  = (const float*)d_in[0];
    const float* vec  = (const float*)d_in[1];
    const int*   mask = (const int*)d_in[2];

    float* out_pooled  = (float*)d_out;               // [B, D]
    float* out_weights = out_pooled + (size_t)B * D;  // [B, L]

    attn_pool_pass1<<<B * NCHUNK, THREADS1>>>(seq, vec, mask);
    attn_pool_pass2<<<B * P2_SPLIT, THREADS2>>>(out_pooled, out_weights);
}